// round 8
// baseline (speedup 1.0000x reference)
#include <cuda_runtime.h>
#include <cuda_fp16.h>
#include <math.h>
#include <stdint.h>

#define NJ    24
#define DIN   256
#define NTOK  1152
#define MROWS 18432
#define EPSV  1e-6f

__device__ __half g_wt[3 * DIN * DIN];                      /* [sel*256+n][k] fp16 */
__device__ __half g_qkv[3ull * 16 * 8 * NTOK * 32];         /* [sel*128+b*8+h][tok][32] fp16 */

/* ---------------- W transpose+convert: 32x32 smem tiles ---------------- */
__global__ __launch_bounds__(256) void wcvt_kernel(
    const float* __restrict__ Wq, const float* __restrict__ Wk, const float* __restrict__ Wv)
{
    __shared__ float t[32][33];
    const int sel = blockIdx.z;
    const float* W = (sel == 0) ? Wq : (sel == 1 ? Wk : Wv);
    const int n0 = blockIdx.x * 32, k0 = blockIdx.y * 32;
    const int tx = threadIdx.x, ty = threadIdx.y;
#pragma unroll
    for (int i = 0; i < 4; i++)
        t[ty + i * 8][tx] = W[(size_t)(k0 + ty + i * 8) * 256 + n0 + tx];
    __syncthreads();
#pragma unroll
    for (int i = 0; i < 4; i++)
        g_wt[sel * 65536 + (size_t)(n0 + ty + i * 8) * 256 + k0 + tx] =
            __float2half_rn(t[tx][ty + i * 8]);
}

/* ---------------- PTX helpers ---------------- */
__device__ __forceinline__ void mma16816(float* c, const uint32_t* a, const uint32_t* b) {
    asm volatile("mma.sync.aligned.m16n8k16.row.col.f32.f16.f16.f32 "
        "{%0,%1,%2,%3}, {%4,%5,%6,%7}, {%8,%9}, {%0,%1,%2,%3};"
        : "+f"(c[0]), "+f"(c[1]), "+f"(c[2]), "+f"(c[3])
        : "r"(a[0]), "r"(a[1]), "r"(a[2]), "r"(a[3]), "r"(b[0]), "r"(b[1]));
}
__device__ __forceinline__ void ldsm_x4(uint32_t* r, uint32_t addr) {
    asm volatile("ldmatrix.sync.aligned.m8n8.x4.shared.b16 {%0,%1,%2,%3}, [%4];"
        : "=r"(r[0]), "=r"(r[1]), "=r"(r[2]), "=r"(r[3]) : "r"(addr));
}
__device__ __forceinline__ void cp16(uint32_t dst, const void* src) {
    asm volatile("cp.async.cg.shared.global [%0], [%1], 16;" :: "r"(dst), "l"(src));
}
#define CP_COMMIT() asm volatile("cp.async.commit_group;" ::: "memory")
#define CP_WAIT(n)  asm volatile("cp.async.wait_group %0;" :: "n"(n) : "memory")
__device__ __forceinline__ uint32_t smem_u32(const void* p) {
    uint32_t a;
    asm("{ .reg .u64 t; cvta.to.shared.u64 t, %1; cvt.u32.u64 %0, t; }" : "=r"(a) : "l"(p));
    return a;
}

/* ---------------- fp16 GEMM: resident A (64 rows), loop full N ----------------
 * C[18432,768] = x @ Wcat^T. 288 CTAs x 64 rows. 8 warps (2m x 4n), warp 32x32.
 * A: fp32 loaded ONCE, fp16 resident smem [64][264]. B: 24 stages (6 nc x 4 k64),
 * cp.async double-buffered, stride 72 halves. Epilogue per n-chunk -> fp16 head-major.
 */
#define M_CTA 64
#define AST   264
#define A_BYTES   (M_CTA * AST * 2)        /* 33792 */
#define B_STAGE   (128 * 72 * 2)           /* 18432 */
#define B_OFF     A_BYTES
#define BIAS_OFF  (A_BYTES + 2 * B_STAGE)  /* 70656 */
#define SMEM_GEMM (BIAS_OFF + 768 * 4)     /* 73728 -> 2 CTAs/SM */

__global__ __launch_bounds__(256) void gemm_kernel(
    const float* __restrict__ x,
    const float* __restrict__ bq, const float* __restrict__ bk, const float* __restrict__ bv)
{
    extern __shared__ char smc[];
    const uint32_t sb = smem_u32(smc);
    __half* Ah = (__half*)smc;
    float* sbias = (float*)(smc + BIAS_OFF);

    const int tid  = threadIdx.x;
    const int wid  = tid >> 5, lane = tid & 31;
    const int gid  = lane >> 2, tig = lane & 3;
    const int m0   = blockIdx.x * M_CTA;
    const int mwarp = wid & 1;              /* 2 m-warps x 4 n-warps */
    const int nwarp = wid >> 1;

    const int mq = lane >> 3;
    const int laneRowA = (mq & 1) * 8 + (lane & 7);
    const int laneColA = (mq >> 1) * 8;
    const int laneRowB = (mq >> 1) * 8 + (lane & 7);
    const int laneColB = (mq & 1) * 8;

    /* stage s = nc*4 + ch : B tile 128n x 64k */
    auto stageB = [&](int s, int buf) {
        const int nc = s >> 2, ch = s & 3;
        const __half* src = g_wt + (size_t)(nc * 128 + (tid >> 1)) * 256 + ch * 64 + (tid & 1) * 32;
        uint32_t dst = sb + B_OFF + (uint32_t)buf * B_STAGE + (uint32_t)(tid >> 1) * 144 + (tid & 1) * 64;
        cp16(dst,      src);
        cp16(dst + 16, src + 8);
        cp16(dst + 32, src + 16);
        cp16(dst + 48, src + 24);
    };

    stageB(0, 0);
    CP_COMMIT();

    /* A prologue: x slice fp32 -> fp16 resident (loaded once) */
#pragma unroll
    for (int i = 0; i < 16; i++) {
        int idx = i * 256 + tid;
        int row = idx >> 6, c4 = idx & 63;
        float4 v = *(const float4*)(x + (size_t)(m0 + row) * 256 + c4 * 4);
        __half2 h0 = __floats2half2_rn(v.x, v.y);
        __half2 h1 = __floats2half2_rn(v.z, v.w);
        uint2 pk;
        pk.x = *(uint32_t*)&h0;
        pk.y = *(uint32_t*)&h1;
        *(uint2*)(Ah + row * AST + c4 * 4) = pk;
    }
    sbias[tid]       = bq[tid];
    sbias[256 + tid] = bk[tid];
    sbias[512 + tid] = bv[tid];

    const int bb = m0 / NTOK;
    const int tokbase = m0 % NTOK;

    float c[2][4][4];

#pragma unroll 1
    for (int s = 0; s < 24; s++) {
        if (s < 23) { stageB(s + 1, (s + 1) & 1); CP_COMMIT(); CP_WAIT(1); }
        else        { CP_WAIT(0); }
        __syncthreads();

        if ((s & 3) == 0) {
#pragma unroll
            for (int mt = 0; mt < 2; mt++)
#pragma unroll
                for (int nt = 0; nt < 4; nt++)
#pragma unroll
                    for (int q = 0; q < 4; q++) c[mt][nt][q] = 0.f;
        }

        const int ch = s & 3;
        const uint32_t bBase = sb + B_OFF + (uint32_t)(s & 1) * B_STAGE;
#pragma unroll
        for (int ks = 0; ks < 4; ks++) {
            uint32_t a[2][4];
#pragma unroll
            for (int mt = 0; mt < 2; mt++) {
                uint32_t ao = (uint32_t)((mwarp * 32 + mt * 16 + laneRowA) * AST
                                         + ch * 64 + ks * 16 + laneColA) * 2;
                ldsm_x4(a[mt], sb + ao);
            }
#pragma unroll
            for (int ntp = 0; ntp < 2; ntp++) {
                uint32_t bo = (uint32_t)((nwarp * 32 + ntp * 16 + laneRowB) * 72
                                         + ks * 16 + laneColB) * 2;
                uint32_t bfr[4];
                ldsm_x4(bfr, bBase + bo);
#pragma unroll
                for (int mt = 0; mt < 2; mt++) {
                    mma16816(c[mt][2 * ntp],     a[mt], bfr);
                    mma16816(c[mt][2 * ntp + 1], a[mt], bfr + 2);
                }
            }
        }

        if ((s & 3) == 3) {                  /* epilogue for n-chunk nc */
            const int nc = s >> 2, sel = nc >> 1;
            __half* outsel = g_qkv + (size_t)(sel * 128 + bb * 8) * NTOK * 32;
#pragma unroll
            for (int mt = 0; mt < 2; mt++) {
                int r0 = tokbase + mwarp * 32 + mt * 16 + gid;
#pragma unroll
                for (int nt = 0; nt < 4; nt++) {
                    int cl = nwarp * 32 + nt * 8 + tig * 2;      /* 0..127 */
                    int gcol = nc * 128 + cl;                    /* 0..767 */
                    int colsel = (nc & 1) * 128 + cl;
                    int h = colsel >> 5, d = colsel & 31;
                    float bi0 = sbias[gcol], bi1 = sbias[gcol + 1];
                    float v0 = c[mt][nt][0] + bi0, v1 = c[mt][nt][1] + bi1;
                    float v2 = c[mt][nt][2] + bi0, v3 = c[mt][nt][3] + bi1;
                    if (sel == 2) {
                        v0 = fmaxf(v0, 0.f); v1 = fmaxf(v1, 0.f);
                        v2 = fmaxf(v2, 0.f); v3 = fmaxf(v3, 0.f);
                    }
                    __half* p0 = outsel + ((size_t)h * NTOK + r0) * 32 + d;
                    *(__half2*)p0            = __floats2half2_rn(v0, v1);
                    *(__half2*)(p0 + 8 * 32) = __floats2half2_rn(v2, v3);
                }
            }
        }
        __syncthreads();
    }
}

/* ---------------- attention: warp per (b, h, frame), fp16 QKV in ---------- */
#define SWST 28

__global__ __launch_bounds__(256) void attn_kernel(float* __restrict__ out)
{
    __shared__ float sw[8 * 32 * SWST];
    const int bh   = blockIdx.x;
    const int wid  = threadIdx.x >> 5;
    const int lane = threadIdx.x & 31;
    const int frame = blockIdx.y * 8 + wid;

    const __half* qb = g_qkv + ((size_t)bh * NTOK + (size_t)frame * NJ) * 32;
    const __half* kb = g_qkv + ((size_t)(128 + bh) * NTOK + (size_t)frame * NJ) * 32;
    const __half* vb = g_qkv + ((size_t)(256 + bh) * NTOK + (size_t)frame * NJ) * 32;

    float* sc = sw + wid * 32 * SWST;

#pragma unroll
    for (int r = 0; r < NJ; r++)
        sc[lane * SWST + r] = __half2float(qb[r * 32 + lane]);
    __syncwarp();

    const int j = (lane < NJ) ? lane : 0;
    float kreg[32];
    {
        const __half2* kp = (const __half2*)(kb + j * 32);
#pragma unroll
        for (int cc = 0; cc < 16; cc++) {
            float2 fv = __half22float2(kp[cc]);
            kreg[2 * cc] = fv.x; kreg[2 * cc + 1] = fv.y;
        }
    }
    float s[NJ];
#pragma unroll
    for (int i = 0; i < NJ; i++) s[i] = 0.f;
#pragma unroll
    for (int d = 0; d < 32; d++) {
        float kd = kreg[d];
#pragma unroll
        for (int i4 = 0; i4 < 6; i4++) {
            float4 q4 = *(const float4*)&sc[d * SWST + i4 * 4];
            s[i4*4+0] = fmaf(q4.x, kd, s[i4*4+0]);
            s[i4*4+1] = fmaf(q4.y, kd, s[i4*4+1]);
            s[i4*4+2] = fmaf(q4.z, kd, s[i4*4+2]);
            s[i4*4+3] = fmaf(q4.w, kd, s[i4*4+3]);
        }
    }
    const float scale = 0.17677669529663688f;
#pragma unroll
    for (int i = 0; i < NJ; i++)
        s[i] = (lane < NJ) ? s[i] * scale : -3.402823466e38f;

    __syncwarp();
    float w_[NJ];
#pragma unroll
    for (int i = 0; i < NJ; i++) {
        float m = s[i];
#pragma unroll
        for (int off = 16; off > 0; off >>= 1)
            m = fmaxf(m, __shfl_xor_sync(0xffffffffu, m, off));
        float e = __expf(s[i] - m);
        float sum = e;
#pragma unroll
        for (int off = 16; off > 0; off >>= 1)
            sum += __shfl_xor_sync(0xffffffffu, sum, off);
        w_[i] = e / (sum + EPSV);
    }

    if (lane < NJ) {
#pragma unroll
        for (int i = 0; i < NJ; i++)
            sc[lane * SWST + i] = w_[i];
    }
    __syncwarp();

    float vreg[NJ];
#pragma unroll
    for (int jj = 0; jj < NJ; jj++)
        vreg[jj] = __half2float(vb[jj * 32 + lane]);
    float o[NJ];
#pragma unroll
    for (int i = 0; i < NJ; i++) o[i] = 0.f;
#pragma unroll
    for (int jj = 0; jj < NJ; jj++) {
        float vj = vreg[jj];
#pragma unroll
        for (int i4 = 0; i4 < 6; i4++) {
            float4 a4 = *(const float4*)&sc[jj * SWST + i4 * 4];
            o[i4*4+0] = fmaf(a4.x, vj, o[i4*4+0]);
            o[i4*4+1] = fmaf(a4.y, vj, o[i4*4+1]);
            o[i4*4+2] = fmaf(a4.z, vj, o[i4*4+2]);
            o[i4*4+3] = fmaf(a4.w, vj, o[i4*4+3]);
        }
    }

    const int b = bh >> 3, h = bh & 7;
    float* od = out + ((size_t)b * NTOK + (size_t)frame * NJ) * DIN + h * 32 + lane;
#pragma unroll
    for (int i = 0; i < NJ; i++)
        od[(size_t)i * DIN] = o[i];
}

/* ---------------- launch ---------------- */
extern "C" void kernel_launch(void* const* d_in, const int* in_sizes, int n_in,
                              void* d_out, int out_size)
{
    const float* x  = (const float*)d_in[0];
    const float* Wq = (const float*)d_in[1];
    const float* bq = (const float*)d_in[2];
    const float* Wk = (const float*)d_in[3];
    const float* bk = (const float*)d_in[4];
    const float* Wv = (const float*)d_in[5];
    const float* bv = (const float*)d_in[6];
    float* out = (float*)d_out;

    wcvt_kernel<<<dim3(8, 8, 3), dim3(32, 8)>>>(Wq, Wk, Wv);

    cudaFuncSetAttribute(gemm_kernel, cudaFuncAttributeMaxDynamicSharedMemorySize, SMEM_GEMM);
    gemm_kernel<<<MROWS / M_CTA, 256, SMEM_GEMM>>>(x, bq, bk, bv);

    attn_kernel<<<dim3(128, 6), 256>>>(out);
}

// round 10
// speedup vs baseline: 1.0663x; 1.0663x over previous
#include <cuda_runtime.h>
#include <cuda_fp16.h>
#include <math.h>
#include <stdint.h>

#define NJ    24
#define DIN   256
#define NTOK  1152
#define MROWS 18432
#define EPSV  1e-6f

__device__ __half g_wt[3 * DIN * DIN];                      /* [sel*256+n][k] fp16 */
__device__ __half g_qkv[3ull * 16 * 8 * NTOK * 32];         /* [sel*128+b*8+h][tok][32] fp16 */

/* ---------------- W transpose+convert: 32x32 smem tiles ---------------- */
__global__ __launch_bounds__(256) void wcvt_kernel(
    const float* __restrict__ Wq, const float* __restrict__ Wk, const float* __restrict__ Wv)
{
    __shared__ float t[32][33];
    const int sel = blockIdx.z;
    const float* W = (sel == 0) ? Wq : (sel == 1 ? Wk : Wv);
    const int n0 = blockIdx.x * 32, k0 = blockIdx.y * 32;
    const int tx = threadIdx.x, ty = threadIdx.y;
#pragma unroll
    for (int i = 0; i < 4; i++)
        t[ty + i * 8][tx] = W[(size_t)(k0 + ty + i * 8) * 256 + n0 + tx];
    __syncthreads();
#pragma unroll
    for (int i = 0; i < 4; i++)
        g_wt[sel * 65536 + (size_t)(n0 + ty + i * 8) * 256 + k0 + tx] =
            __float2half_rn(t[tx][ty + i * 8]);
}

/* ---------------- PTX helpers ---------------- */
__device__ __forceinline__ void mma16816(float* c, const uint32_t* a, const uint32_t* b) {
    asm volatile("mma.sync.aligned.m16n8k16.row.col.f32.f16.f16.f32 "
        "{%0,%1,%2,%3}, {%4,%5,%6,%7}, {%8,%9}, {%0,%1,%2,%3};"
        : "+f"(c[0]), "+f"(c[1]), "+f"(c[2]), "+f"(c[3])
        : "r"(a[0]), "r"(a[1]), "r"(a[2]), "r"(a[3]), "r"(b[0]), "r"(b[1]));
}
__device__ __forceinline__ void ldsm_x4(uint32_t* r, uint32_t addr) {
    asm volatile("ldmatrix.sync.aligned.m8n8.x4.shared.b16 {%0,%1,%2,%3}, [%4];"
        : "=r"(r[0]), "=r"(r[1]), "=r"(r[2]), "=r"(r[3]) : "r"(addr));
}
__device__ __forceinline__ void cp16(uint32_t dst, const void* src) {
    asm volatile("cp.async.cg.shared.global [%0], [%1], 16;" :: "r"(dst), "l"(src));
}
#define CP_COMMIT() asm volatile("cp.async.commit_group;" ::: "memory")
#define CP_WAIT(n)  asm volatile("cp.async.wait_group %0;" :: "n"(n) : "memory")
__device__ __forceinline__ uint32_t smem_u32(const void* p) {
    uint32_t a;
    asm("{ .reg .u64 t; cvta.to.shared.u64 t, %1; cvt.u32.u64 %0, t; }" : "=r"(a) : "l"(p));
    return a;
}

/* ---------------- fp16 GEMM: single wave, n-chunk stages ----------------
 * C[18432,768] = x @ Wcat^T. 144 CTAs x 128 rows (one per SM, one wave).
 * A resident fp16 [128][264]. B: 6 stages of full 128x256 n-chunks,
 * cp.async double-buffered, stride 264 halves. 256 MMAs/warp/stage.
 */
#define AST   264
#define A_BYTES   (128 * AST * 2)          /* 67584 */
#define B_BUF     (128 * AST * 2)          /* 67584 */
#define B_OFF     A_BYTES
#define BIAS_OFF  (A_BYTES + 2 * B_BUF)    /* 202752 */
#define SMEM_GEMM (BIAS_OFF + 768 * 4)     /* 205824 */

__global__ __launch_bounds__(256) void gemm_kernel(
    const float* __restrict__ x,
    const float* __restrict__ bq, const float* __restrict__ bk, const float* __restrict__ bv)
{
    extern __shared__ char smc[];
    const uint32_t sb = smem_u32(smc);
    __half* Ah = (__half*)smc;
    float* sbias = (float*)(smc + BIAS_OFF);

    const int tid  = threadIdx.x;
    const int wid  = tid >> 5, lane = tid & 31;
    const int gid  = lane >> 2, tig = lane & 3;
    const int m0   = blockIdx.x * 128;
    const int rbase = (wid & 3) * 32;          /* 4 m-warps */
    const int nbase = (wid >> 2) * 64;         /* 2 n-warps */

    const int mq = lane >> 3;
    const int laneRowA = (mq & 1) * 8 + (lane & 7);
    const int laneColA = (mq >> 1) * 8;
    const int laneRowB = (mq >> 1) * 8 + (lane & 7);
    const int laneColB = (mq & 1) * 8;

    /* stage full n-chunk nc: 128 rows x 256 halves. thread t: row t>>1, half (t&1) */
    auto stageB = [&](int nc, int buf) {
        const __half* src = g_wt + (size_t)(nc * 128 + (tid >> 1)) * 256 + (tid & 1) * 128;
        uint32_t dst = sb + B_OFF + (uint32_t)buf * B_BUF
                     + (uint32_t)(tid >> 1) * (AST * 2) + (tid & 1) * 256;
#pragma unroll
        for (int i = 0; i < 16; i++)
            cp16(dst + i * 16, src + i * 8);
    };

    stageB(0, 0);
    CP_COMMIT();

    /* A prologue: x slice fp32 -> fp16 resident (loaded once) */
#pragma unroll
    for (int i = 0; i < 32; i++) {
        int idx = i * 256 + tid;
        int row = idx >> 6, c4 = idx & 63;
        float4 v = *(const float4*)(x + (size_t)(m0 + row) * 256 + c4 * 4);
        __half2 h0 = __floats2half2_rn(v.x, v.y);
        __half2 h1 = __floats2half2_rn(v.z, v.w);
        uint2 pk;
        pk.x = *(uint32_t*)&h0;
        pk.y = *(uint32_t*)&h1;
        *(uint2*)(Ah + row * AST + c4 * 4) = pk;
    }
    sbias[tid]       = bq[tid];
    sbias[256 + tid] = bk[tid];
    sbias[512 + tid] = bv[tid];

    const int bb = m0 / NTOK;
    const int tokbase = m0 % NTOK;

    float c[2][8][4];

#pragma unroll 1
    for (int nc = 0; nc < 6; nc++) {
        if (nc < 5) { stageB(nc + 1, (nc + 1) & 1); CP_COMMIT(); CP_WAIT(1); }
        else        { CP_WAIT(0); }
        __syncthreads();

#pragma unroll
        for (int mt = 0; mt < 2; mt++)
#pragma unroll
            for (int nt = 0; nt < 8; nt++)
#pragma unroll
                for (int q = 0; q < 4; q++) c[mt][nt][q] = 0.f;

        const uint32_t bBase = sb + B_OFF + (uint32_t)(nc & 1) * B_BUF;
#pragma unroll 4
        for (int ks = 0; ks < 16; ks++) {
            uint32_t a[2][4];
#pragma unroll
            for (int mt = 0; mt < 2; mt++) {
                uint32_t ao = (uint32_t)((rbase + mt * 16 + laneRowA) * AST
                                         + ks * 16 + laneColA) * 2;
                ldsm_x4(a[mt], sb + ao);
            }
#pragma unroll
            for (int ntp = 0; ntp < 4; ntp++) {
                uint32_t bo = (uint32_t)((nbase + ntp * 16 + laneRowB) * AST
                                         + ks * 16 + laneColB) * 2;
                uint32_t bfr[4];
                ldsm_x4(bfr, bBase + bo);
#pragma unroll
                for (int mt = 0; mt < 2; mt++) {
                    mma16816(c[mt][2 * ntp],     a[mt], bfr);
                    mma16816(c[mt][2 * ntp + 1], a[mt], bfr + 2);
                }
            }
        }

        /* epilogue for n-chunk nc: bias (+relu V), fp16 head-major */
        {
            const int sel = nc >> 1;
            __half* outsel = g_qkv + (size_t)(sel * 128 + bb * 8) * NTOK * 32;
#pragma unroll
            for (int mt = 0; mt < 2; mt++) {
                int r0 = tokbase + rbase + mt * 16 + gid;
#pragma unroll
                for (int nt = 0; nt < 8; nt++) {
                    int cl = nbase + nt * 8 + tig * 2;       /* 0..127 */
                    int gcol = nc * 128 + cl;
                    int colsel = (nc & 1) * 128 + cl;
                    int h = colsel >> 5, d = colsel & 31;
                    float bi0 = sbias[gcol], bi1 = sbias[gcol + 1];
                    float v0 = c[mt][nt][0] + bi0, v1 = c[mt][nt][1] + bi1;
                    float v2 = c[mt][nt][2] + bi0, v3 = c[mt][nt][3] + bi1;
                    if (sel == 2) {
                        v0 = fmaxf(v0, 0.f); v1 = fmaxf(v1, 0.f);
                        v2 = fmaxf(v2, 0.f); v3 = fmaxf(v3, 0.f);
                    }
                    __half* p0 = outsel + ((size_t)h * NTOK + r0) * 32 + d;
                    *(__half2*)p0            = __floats2half2_rn(v0, v1);
                    *(__half2*)(p0 + 8 * 32) = __floats2half2_rn(v2, v3);
                }
            }
        }
        __syncthreads();
    }
}

/* ---------------- attention: warp per (b, h, frame), fp16 QKV in ---------- */
#define SWST 28

__global__ __launch_bounds__(256) void attn_kernel(float* __restrict__ out)
{
    __shared__ float sw[8 * 32 * SWST];
    const int bh   = blockIdx.x;
    const int wid  = threadIdx.x >> 5;
    const int lane = threadIdx.x & 31;
    const int frame = blockIdx.y * 8 + wid;

    const __half* qb = g_qkv + ((size_t)bh * NTOK + (size_t)frame * NJ) * 32;
    const __half* kb = g_qkv + ((size_t)(128 + bh) * NTOK + (size_t)frame * NJ) * 32;
    const __half* vb = g_qkv + ((size_t)(256 + bh) * NTOK + (size_t)frame * NJ) * 32;

    float* sc = sw + wid * 32 * SWST;

#pragma unroll
    for (int r = 0; r < NJ; r++)
        sc[lane * SWST + r] = __half2float(qb[r * 32 + lane]);
    __syncwarp();

    const int j = (lane < NJ) ? lane : 0;
    float kreg[32];
    {
        const __half2* kp = (const __half2*)(kb + j * 32);
#pragma unroll
        for (int cc = 0; cc < 16; cc++) {
            float2 fv = __half22float2(kp[cc]);
            kreg[2 * cc] = fv.x; kreg[2 * cc + 1] = fv.y;
        }
    }
    float s[NJ];
#pragma unroll
    for (int i = 0; i < NJ; i++) s[i] = 0.f;
#pragma unroll
    for (int d = 0; d < 32; d++) {
        float kd = kreg[d];
#pragma unroll
        for (int i4 = 0; i4 < 6; i4++) {
            float4 q4 = *(const float4*)&sc[d * SWST + i4 * 4];
            s[i4*4+0] = fmaf(q4.x, kd, s[i4*4+0]);
            s[i4*4+1] = fmaf(q4.y, kd, s[i4*4+1]);
            s[i4*4+2] = fmaf(q4.z, kd, s[i4*4+2]);
            s[i4*4+3] = fmaf(q4.w, kd, s[i4*4+3]);
        }
    }
    const float scale = 0.17677669529663688f;
#pragma unroll
    for (int i = 0; i < NJ; i++)
        s[i] = (lane < NJ) ? s[i] * scale : -3.402823466e38f;

    __syncwarp();
    float w_[NJ];
#pragma unroll
    for (int i = 0; i < NJ; i++) {
        float m = s[i];
#pragma unroll
        for (int off = 16; off > 0; off >>= 1)
            m = fmaxf(m, __shfl_xor_sync(0xffffffffu, m, off));
        float e = __expf(s[i] - m);
        float sum = e;
#pragma unroll
        for (int off = 16; off > 0; off >>= 1)
            sum += __shfl_xor_sync(0xffffffffu, sum, off);
        w_[i] = e / (sum + EPSV);
    }

    if (lane < NJ) {
#pragma unroll
        for (int i = 0; i < NJ; i++)
            sc[lane * SWST + i] = w_[i];
    }
    __syncwarp();

    float vreg[NJ];
#pragma unroll
    for (int jj = 0; jj < NJ; jj++)
        vreg[jj] = __half2float(vb[jj * 32 + lane]);
    float o[NJ];
#pragma unroll
    for (int i = 0; i < NJ; i++) o[i] = 0.f;
#pragma unroll
    for (int jj = 0; jj < NJ; jj++) {
        float vj = vreg[jj];
#pragma unroll
        for (int i4 = 0; i4 < 6; i4++) {
            float4 a4 = *(const float4*)&sc[jj * SWST + i4 * 4];
            o[i4*4+0] = fmaf(a4.x, vj, o[i4*4+0]);
            o[i4*4+1] = fmaf(a4.y, vj, o[i4*4+1]);
            o[i4*4+2] = fmaf(a4.z, vj, o[i4*4+2]);
            o[i4*4+3] = fmaf(a4.w, vj, o[i4*4+3]);
        }
    }

    const int b = bh >> 3, h = bh & 7;
    float* od = out + ((size_t)b * NTOK + (size_t)frame * NJ) * DIN + h * 32 + lane;
#pragma unroll
    for (int i = 0; i < NJ; i++)
        od[(size_t)i * DIN] = o[i];
}

/* ---------------- launch ---------------- */
extern "C" void kernel_launch(void* const* d_in, const int* in_sizes, int n_in,
                              void* d_out, int out_size)
{
    const float* x  = (const float*)d_in[0];
    const float* Wq = (const float*)d_in[1];
    const float* bq = (const float*)d_in[2];
    const float* Wk = (const float*)d_in[3];
    const float* bk = (const float*)d_in[4];
    const float* Wv = (const float*)d_in[5];
    const float* bv = (const float*)d_in[6];
    float* out = (float*)d_out;

    wcvt_kernel<<<dim3(8, 8, 3), dim3(32, 8)>>>(Wq, Wk, Wv);

    cudaFuncSetAttribute(gemm_kernel, cudaFuncAttributeMaxDynamicSharedMemorySize, SMEM_GEMM);
    gemm_kernel<<<144, 256, SMEM_GEMM>>>(x, bq, bk, bv);

    attn_kernel<<<dim3(128, 6), 256>>>(out);
}

// round 11
// speedup vs baseline: 1.6419x; 1.5399x over previous
#include <cuda_runtime.h>
#include <cuda_fp16.h>
#include <math.h>
#include <stdint.h>

#define NJ    24
#define DIN   256
#define NTOK  1152
#define MROWS 18432
#define EPSV  1e-6f

__device__ __half g_wt[3 * DIN * DIN];                      /* [sel*256+n][k] fp16 */
__device__ __half g_qkv[3ull * 16 * 8 * NTOK * 32];         /* [sel*128+b*8+h][tok][32] fp16 */

/* ---------------- W transpose+convert: 32x32 smem tiles ---------------- */
__global__ __launch_bounds__(256) void wcvt_kernel(
    const float* __restrict__ Wq, const float* __restrict__ Wk, const float* __restrict__ Wv)
{
    __shared__ float t[32][33];
    const int sel = blockIdx.z;
    const float* W = (sel == 0) ? Wq : (sel == 1 ? Wk : Wv);
    const int n0 = blockIdx.x * 32, k0 = blockIdx.y * 32;
    const int tx = threadIdx.x, ty = threadIdx.y;
#pragma unroll
    for (int i = 0; i < 4; i++)
        t[ty + i * 8][tx] = W[(size_t)(k0 + ty + i * 8) * 256 + n0 + tx];
    __syncthreads();
#pragma unroll
    for (int i = 0; i < 4; i++)
        g_wt[sel * 65536 + (size_t)(n0 + ty + i * 8) * 256 + k0 + tx] =
            __float2half_rn(t[tx][ty + i * 8]);
}

/* ---------------- PTX helpers ---------------- */
__device__ __forceinline__ void mma16816(float* c, const uint32_t* a, const uint32_t* b) {
    asm volatile("mma.sync.aligned.m16n8k16.row.col.f32.f16.f16.f32 "
        "{%0,%1,%2,%3}, {%4,%5,%6,%7}, {%8,%9}, {%0,%1,%2,%3};"
        : "+f"(c[0]), "+f"(c[1]), "+f"(c[2]), "+f"(c[3])
        : "r"(a[0]), "r"(a[1]), "r"(a[2]), "r"(a[3]), "r"(b[0]), "r"(b[1]));
}
__device__ __forceinline__ void ldsm_x4(uint32_t* r, uint32_t addr) {
    asm volatile("ldmatrix.sync.aligned.m8n8.x4.shared.b16 {%0,%1,%2,%3}, [%4];"
        : "=r"(r[0]), "=r"(r[1]), "=r"(r[2]), "=r"(r[3]) : "r"(addr));
}
__device__ __forceinline__ void ldsm_x4_t(uint32_t* r, uint32_t addr) {
    asm volatile("ldmatrix.sync.aligned.m8n8.x4.trans.shared.b16 {%0,%1,%2,%3}, [%4];"
        : "=r"(r[0]), "=r"(r[1]), "=r"(r[2]), "=r"(r[3]) : "r"(addr));
}
__device__ __forceinline__ void cp16(uint32_t dst, const void* src) {
    asm volatile("cp.async.cg.shared.global [%0], [%1], 16;" :: "r"(dst), "l"(src));
}
#define CP_COMMIT() asm volatile("cp.async.commit_group;" ::: "memory")
#define CP_WAIT(n)  asm volatile("cp.async.wait_group %0;" :: "n"(n) : "memory")
__device__ __forceinline__ uint32_t smem_u32(const void* p) {
    uint32_t a;
    asm("{ .reg .u64 t; cvta.to.shared.u64 t, %1; cvt.u32.u64 %0, t; }" : "=r"(a) : "l"(p));
    return a;
}

/* ---------------- fp16 GEMM: single wave, n-chunk stages (R10, passing) ------ */
#define AST   264
#define A_BYTES   (128 * AST * 2)          /* 67584 */
#define B_BUF     (128 * AST * 2)          /* 67584 */
#define B_OFF     A_BYTES
#define BIAS_OFF  (A_BYTES + 2 * B_BUF)    /* 202752 */
#define SMEM_GEMM (BIAS_OFF + 768 * 4)     /* 205824 */

__global__ __launch_bounds__(256) void gemm_kernel(
    const float* __restrict__ x,
    const float* __restrict__ bq, const float* __restrict__ bk, const float* __restrict__ bv)
{
    extern __shared__ char smc[];
    const uint32_t sb = smem_u32(smc);
    __half* Ah = (__half*)smc;
    float* sbias = (float*)(smc + BIAS_OFF);

    const int tid  = threadIdx.x;
    const int wid  = tid >> 5, lane = tid & 31;
    const int gid  = lane >> 2, tig = lane & 3;
    const int m0   = blockIdx.x * 128;
    const int rbase = (wid & 3) * 32;
    const int nbase = (wid >> 2) * 64;

    const int mq = lane >> 3;
    const int laneRowA = (mq & 1) * 8 + (lane & 7);
    const int laneColA = (mq >> 1) * 8;
    const int laneRowB = (mq >> 1) * 8 + (lane & 7);
    const int laneColB = (mq & 1) * 8;

    auto stageB = [&](int nc, int buf) {
        const __half* src = g_wt + (size_t)(nc * 128 + (tid >> 1)) * 256 + (tid & 1) * 128;
        uint32_t dst = sb + B_OFF + (uint32_t)buf * B_BUF
                     + (uint32_t)(tid >> 1) * (AST * 2) + (tid & 1) * 256;
#pragma unroll
        for (int i = 0; i < 16; i++)
            cp16(dst + i * 16, src + i * 8);
    };

    stageB(0, 0);
    CP_COMMIT();

#pragma unroll
    for (int i = 0; i < 32; i++) {
        int idx = i * 256 + tid;
        int row = idx >> 6, c4 = idx & 63;
        float4 v = *(const float4*)(x + (size_t)(m0 + row) * 256 + c4 * 4);
        __half2 h0 = __floats2half2_rn(v.x, v.y);
        __half2 h1 = __floats2half2_rn(v.z, v.w);
        uint2 pk;
        pk.x = *(uint32_t*)&h0;
        pk.y = *(uint32_t*)&h1;
        *(uint2*)(Ah + row * AST + c4 * 4) = pk;
    }
    sbias[tid]       = bq[tid];
    sbias[256 + tid] = bk[tid];
    sbias[512 + tid] = bv[tid];

    const int bb = m0 / NTOK;
    const int tokbase = m0 % NTOK;

    float c[2][8][4];

#pragma unroll 1
    for (int nc = 0; nc < 6; nc++) {
        if (nc < 5) { stageB(nc + 1, (nc + 1) & 1); CP_COMMIT(); CP_WAIT(1); }
        else        { CP_WAIT(0); }
        __syncthreads();

#pragma unroll
        for (int mt = 0; mt < 2; mt++)
#pragma unroll
            for (int nt = 0; nt < 8; nt++)
#pragma unroll
                for (int q = 0; q < 4; q++) c[mt][nt][q] = 0.f;

        const uint32_t bBase = sb + B_OFF + (uint32_t)(nc & 1) * B_BUF;
#pragma unroll 4
        for (int ks = 0; ks < 16; ks++) {
            uint32_t a[2][4];
#pragma unroll
            for (int mt = 0; mt < 2; mt++) {
                uint32_t ao = (uint32_t)((rbase + mt * 16 + laneRowA) * AST
                                         + ks * 16 + laneColA) * 2;
                ldsm_x4(a[mt], sb + ao);
            }
#pragma unroll
            for (int ntp = 0; ntp < 4; ntp++) {
                uint32_t bo = (uint32_t)((nbase + ntp * 16 + laneRowB) * AST
                                         + ks * 16 + laneColB) * 2;
                uint32_t bfr[4];
                ldsm_x4(bfr, bBase + bo);
#pragma unroll
                for (int mt = 0; mt < 2; mt++) {
                    mma16816(c[mt][2 * ntp],     a[mt], bfr);
                    mma16816(c[mt][2 * ntp + 1], a[mt], bfr + 2);
                }
            }
        }

        {
            const int sel = nc >> 1;
            __half* outsel = g_qkv + (size_t)(sel * 128 + bb * 8) * NTOK * 32;
#pragma unroll
            for (int mt = 0; mt < 2; mt++) {
                int r0 = tokbase + rbase + mt * 16 + gid;
#pragma unroll
                for (int nt = 0; nt < 8; nt++) {
                    int cl = nbase + nt * 8 + tig * 2;
                    int gcol = nc * 128 + cl;
                    int colsel = (nc & 1) * 128 + cl;
                    int h = colsel >> 5, d = colsel & 31;
                    float bi0 = sbias[gcol], bi1 = sbias[gcol + 1];
                    float v0 = c[mt][nt][0] + bi0, v1 = c[mt][nt][1] + bi1;
                    float v2 = c[mt][nt][2] + bi0, v3 = c[mt][nt][3] + bi1;
                    if (sel == 2) {
                        v0 = fmaxf(v0, 0.f); v1 = fmaxf(v1, 0.f);
                        v2 = fmaxf(v2, 0.f); v3 = fmaxf(v3, 0.f);
                    }
                    __half* p0 = outsel + ((size_t)h * NTOK + r0) * 32 + d;
                    *(__half2*)p0            = __floats2half2_rn(v0, v1);
                    *(__half2*)(p0 + 8 * 32) = __floats2half2_rn(v2, v3);
                }
            }
        }
        __syncthreads();
    }
}

/* ---------------- tensor-core attention ----------------
 * block = (frame, b), 8 warps = 8 heads. QKV staged to smem [head][24 rows][40 halves].
 * S = Q K^T (12 MMAs, M pad 24->32 via address clamp), fragment softmax (+eps),
 * P fp16 via C->A repack, O = P V (16 MMAs, V via ldmatrix.trans, k-pad zeroed in P).
 */
#define HST 960                  /* halves per head: 24 rows * 40 */

__global__ __launch_bounds__(256, 2) void attn_kernel(float* __restrict__ out)
{
    __shared__ __half Qs[8 * HST], Ks[8 * HST], Vs[8 * HST];
    const int frame = blockIdx.x, b = blockIdx.y;
    const int tid = threadIdx.x, wid = tid >> 5, lane = tid & 31;

    /* stage QKV: 24 segs (sel,h) x 96 uint4, coalesced */
#pragma unroll
    for (int it = 0; it < 9; it++) {
        int idx = it * 256 + tid;
        if (idx < 2304) {
            int seg = idx / 96, u = idx % 96;
            int sel = seg >> 3, hh = seg & 7;
            int j = u >> 2, g = u & 3;
            const uint4* src = (const uint4*)(g_qkv
                + ((size_t)(sel * 128 + b * 8 + hh) * NTOK + frame * NJ + j) * 32 + g * 8);
            __half* dstb = (sel == 0) ? Qs : (sel == 1 ? Ks : Vs);
            *(uint4*)(dstb + hh * HST + j * 40 + g * 8) = *src;
        }
    }
    __syncthreads();

    const int h = wid;
    const uint32_t qb = smem_u32(Qs + h * HST);
    const uint32_t kb = smem_u32(Ks + h * HST);
    const uint32_t vb = smem_u32(Vs + h * HST);
    const int gid = lane >> 2, tig = lane & 3;
    const int mq = lane >> 3;
    const int lr  = (mq & 1) * 8 + (lane & 7);     /* A / V-trans row pattern */
    const int lcA = (mq >> 1) * 8;
    const int lrB = (mq >> 1) * 8 + (lane & 7);    /* K (B) row pattern */
    const int lcB = (mq & 1) * 8;

    /* ---- MMA1: S = Q K^T ---- */
    float cs[2][3][4];
#pragma unroll
    for (int mt = 0; mt < 2; mt++)
#pragma unroll
        for (int nt = 0; nt < 3; nt++)
#pragma unroll
            for (int q = 0; q < 4; q++) cs[mt][nt][q] = 0.f;

#pragma unroll
    for (int kt = 0; kt < 2; kt++) {
        uint32_t bK[6];
        {
            uint32_t t4[4];
            ldsm_x4(t4, kb + (uint32_t)(lrB * 40 + kt * 16 + lcB) * 2);          /* nt0,1 */
            bK[0] = t4[0]; bK[1] = t4[1]; bK[2] = t4[2]; bK[3] = t4[3];
            int r2 = 16 + lrB; if (r2 > 23) r2 = 0;
            ldsm_x4(t4, kb + (uint32_t)(r2 * 40 + kt * 16 + lcB) * 2);           /* nt2 (+pad) */
            bK[4] = t4[0]; bK[5] = t4[1];
        }
#pragma unroll
        for (int mt = 0; mt < 2; mt++) {
            int r = mt * 16 + lr; if (r > 23) r = 0;
            uint32_t aQ[4];
            ldsm_x4(aQ, qb + (uint32_t)(r * 40 + kt * 16 + lcA) * 2);
            mma16816(cs[mt][0], aQ, bK);
            mma16816(cs[mt][1], aQ, bK + 2);
            mma16816(cs[mt][2], aQ, bK + 4);
        }
    }

    /* ---- softmax on fragments + P (fp16 A-frags) ---- */
    const float scale = 0.17677669529663688f;   /* 1/sqrt(32) */
    uint32_t aP[2][2][4];
#pragma unroll
    for (int mt = 0; mt < 2; mt++) {
#pragma unroll
        for (int rh = 0; rh < 2; rh++) {
            float v0 = cs[mt][0][2 * rh], v1 = cs[mt][0][2 * rh + 1];
            float v2 = cs[mt][1][2 * rh], v3 = cs[mt][1][2 * rh + 1];
            float v4 = cs[mt][2][2 * rh], v5 = cs[mt][2][2 * rh + 1];
            float m = fmaxf(fmaxf(fmaxf(v0, v1), fmaxf(v2, v3)), fmaxf(v4, v5));
            m = fmaxf(m, __shfl_xor_sync(0xffffffffu, m, 1));
            m = fmaxf(m, __shfl_xor_sync(0xffffffffu, m, 2));
            float e0 = __expf((v0 - m) * scale), e1 = __expf((v1 - m) * scale);
            float e2 = __expf((v2 - m) * scale), e3 = __expf((v3 - m) * scale);
            float e4 = __expf((v4 - m) * scale), e5 = __expf((v5 - m) * scale);
            float s = e0 + e1 + e2 + e3 + e4 + e5;
            s += __shfl_xor_sync(0xffffffffu, s, 1);
            s += __shfl_xor_sync(0xffffffffu, s, 2);
            float inv = 1.0f / (s + EPSV);
            __half2 p01 = __floats2half2_rn(e0 * inv, e1 * inv);
            __half2 p23 = __floats2half2_rn(e2 * inv, e3 * inv);
            __half2 p45 = __floats2half2_rn(e4 * inv, e5 * inv);
            aP[mt][0][0 + rh] = *(uint32_t*)&p01;   /* nt0 -> k 0-7   */
            aP[mt][0][2 + rh] = *(uint32_t*)&p23;   /* nt1 -> k 8-15  */
            aP[mt][1][0 + rh] = *(uint32_t*)&p45;   /* nt2 -> k 16-23 */
            aP[mt][1][2 + rh] = 0u;                 /* k 24-31 pad    */
        }
    }

    /* ---- MMA2: O = P V ---- */
    float co[2][4][4];
#pragma unroll
    for (int mt = 0; mt < 2; mt++)
#pragma unroll
        for (int dt = 0; dt < 4; dt++)
#pragma unroll
            for (int q = 0; q < 4; q++) co[mt][dt][q] = 0.f;

#pragma unroll
    for (int ktj = 0; ktj < 2; ktj++) {
        int jr = ktj * 16 + lr; if (jr > 23) jr = 0;
#pragma unroll
        for (int dp = 0; dp < 2; dp++) {
            uint32_t bV[4];
            ldsm_x4_t(bV, vb + (uint32_t)(jr * 40 + dp * 16 + lcA) * 2);
#pragma unroll
            for (int mt = 0; mt < 2; mt++) {
                mma16816(co[mt][2 * dp],     aP[mt][ktj], bV);
                mma16816(co[mt][2 * dp + 1], aP[mt][ktj], bV + 2);
            }
        }
    }

    /* ---- store O ---- */
    const size_t rowbase = (size_t)b * NTOK + (size_t)frame * NJ;
#pragma unroll
    for (int mt = 0; mt < 2; mt++) {
        int r0 = mt * 16 + gid;            /* always < 24 */
        int r1 = r0 + 8;                   /* mt1 -> 24-31: skip */
#pragma unroll
        for (int dt = 0; dt < 4; dt++) {
            int col = h * 32 + dt * 8 + tig * 2;
            *(float2*)(out + (rowbase + r0) * DIN + col) = make_float2(co[mt][dt][0], co[mt][dt][1]);
            if (mt == 0)
                *(float2*)(out + (rowbase + r1) * DIN + col) = make_float2(co[mt][dt][2], co[mt][dt][3]);
        }
    }
}

/* ---------------- launch ---------------- */
extern "C" void kernel_launch(void* const* d_in, const int* in_sizes, int n_in,
                              void* d_out, int out_size)
{
    const float* x  = (const float*)d_in[0];
    const float* Wq = (const float*)d_in[1];
    const float* bq = (const float*)d_in[2];
    const float* Wk = (const float*)d_in[3];
    const float* bk = (const float*)d_in[4];
    const float* Wv = (const float*)d_in[5];
    const float* bv = (const float*)d_in[6];
    float* out = (float*)d_out;

    wcvt_kernel<<<dim3(8, 8, 3), dim3(32, 8)>>>(Wq, Wk, Wv);

    cudaFuncSetAttribute(gemm_kernel, cudaFuncAttributeMaxDynamicSharedMemorySize, SMEM_GEMM);
    gemm_kernel<<<144, 256, SMEM_GEMM>>>(x, bq, bk, bv);

    attn_kernel<<<dim3(48, 16), 256>>>(out);
}